// round 8
// baseline (speedup 1.0000x reference)
#include <cuda_runtime.h>
#include <math.h>

// SE block: B=32, H=W=56 (HW=3136), C=256, R=16, fp32 NHWC.
// out = in * sigmoid(relu(mean_hw(in) @ W1 + b1) @ W2 + b2)
//
// R7: batch-grouped pipeline. 4 groups x 8 batches (25.7 MB/group << L2).
// pool(g) leaves the group L2-resident; scale(g) re-reads it from L2 and
// streams the output past L2 (st.global.cs). DRAM traffic ~206 MB total.

#define Bb      32
#define Cc      256
#define CR      16
#define HW      3136
#define CQ      64          // C/4 float4 quads per position

#define G       8           // batches per group
#define NGRP    4           // 32 / 8
#define KSPLIT  98          // spatial chunks per batch (pool)
#define CHUNK   32          // 3136 / 98, exact
#define SBLK    98          // scale blocks per batch
#define SSTRIDE (SBLK * 256)  // 25088 quads; % 64 == 0

__device__ float g_partial[Bb * KSPLIT * Cc];   // 3.2 MB scratch
__device__ float g_exc[Bb * Cc];                // 32 KB excitation

__device__ __forceinline__ void stg_cs(float4* p, float4 v) {
    asm volatile("st.global.cs.v4.f32 [%0], {%1,%2,%3,%4};"
                 :: "l"(p), "f"(v.x), "f"(v.y), "f"(v.z), "f"(v.w) : "memory");
}

// ---------------------------------------------------------------------------
// Pool one group: grid (KSPLIT, G) x 256. q = tid&63 channel quad,
// pg = tid>>6 position sub-stream. CHUNK=32 -> exactly 8 loads/thread,
// 2-deep unroll (4 independent LDG.128 streams across the warp), no tail.
// ---------------------------------------------------------------------------
__global__ void __launch_bounds__(256) se_pool_group(const float* __restrict__ in,
                                                     int g)
{
    const int b   = g * G + blockIdx.y;
    const int k   = blockIdx.x;
    const int tid = threadIdx.x;
    const int q   = tid & 63;
    const int pg  = tid >> 6;

    const float4* __restrict__ in4 = reinterpret_cast<const float4*>(in)
                                     + (size_t)b * HW * CQ
                                     + (size_t)(k * CHUNK + pg) * CQ + q;

    float4 a0 = make_float4(0.f, 0.f, 0.f, 0.f);
    float4 a1 = a0;
    #pragma unroll
    for (int t = 0; t < CHUNK / 4; t += 2) {          // 4 iterations, 2 loads each
        float4 v0 = __ldg(in4 + (size_t)(4 * t)     * CQ);
        float4 v1 = __ldg(in4 + (size_t)(4 * t + 4) * CQ);
        a0.x += v0.x; a0.y += v0.y; a0.z += v0.z; a0.w += v0.w;
        a1.x += v1.x; a1.y += v1.y; a1.z += v1.z; a1.w += v1.w;
    }
    a0.x += a1.x; a0.y += a1.y; a0.z += a1.z; a0.w += a1.w;

    __shared__ float4 s[256];
    s[tid] = a0;
    __syncthreads();

    if (tid < 64) {
        float4 a = s[tid];
        float4 c = s[tid + 64];
        float4 d = s[tid + 128];
        float4 e = s[tid + 192];
        float4 r = make_float4(a.x + c.x + d.x + e.x,
                               a.y + c.y + d.y + e.y,
                               a.z + c.z + d.z + e.z,
                               a.w + c.w + d.w + e.w);
        reinterpret_cast<float4*>(g_partial)[(b * KSPLIT + k) * CQ + tid] = r;
    }
}

// ---------------------------------------------------------------------------
// Excite one group: grid = G blocks. Reduce KSPLIT partials -> mean, then
// 256 -> 16 relu -> 256 sigmoid.
// ---------------------------------------------------------------------------
__global__ void __launch_bounds__(256) se_excite_group(const float* __restrict__ W1,
                                                       const float* __restrict__ b1,
                                                       const float* __restrict__ W2,
                                                       const float* __restrict__ b2,
                                                       int g)
{
    const int b = g * G + blockIdx.x;
    const int c = threadIdx.x;

    __shared__ float sq[Cc];
    __shared__ float hs[CR];

    float sum = 0.f;
    #pragma unroll 7
    for (int k = 0; k < KSPLIT; k++)
        sum += g_partial[(b * KSPLIT + k) * Cc + c];
    sq[c] = sum * (1.0f / (float)HW);
    __syncthreads();

    if (c < CR) {
        float h = b1[c];
        #pragma unroll 8
        for (int i = 0; i < Cc; i++)
            h = fmaf(sq[i], W1[i * CR + c], h);
        hs[c] = fmaxf(h, 0.f);
    }
    __syncthreads();

    float e = b2[c];
    #pragma unroll
    for (int j = 0; j < CR; j++)
        e = fmaf(hs[j], W2[j * Cc + c], e);
    g_exc[b * Cc + c] = 1.0f / (1.0f + __expf(-e));
}

// ---------------------------------------------------------------------------
// Scale one group: grid (SBLK, G) x 256, 8 quads/thread at stride 25088.
// Reads should hit L2 (group pooled moments ago); output streams via st.cs.
// ---------------------------------------------------------------------------
__global__ void __launch_bounds__(256) se_scale_group(const float* __restrict__ in,
                                                      float* __restrict__ out,
                                                      int g)
{
    const int b  = g * G + blockIdx.y;
    const int i0 = blockIdx.x * 256 + threadIdx.x;

    const float4* __restrict__ in4  = reinterpret_cast<const float4*>(in)
                                      + (size_t)b * HW * CQ;
    float4* __restrict__       out4 = reinterpret_cast<float4*>(out)
                                      + (size_t)b * HW * CQ;

    const float4 e = __ldg(reinterpret_cast<const float4*>(g_exc)
                           + b * CQ + (threadIdx.x & 63));

    float4 v[8];
    #pragma unroll
    for (int m = 0; m < 8; m++)
        v[m] = __ldg(in4 + i0 + m * SSTRIDE);

    #pragma unroll
    for (int m = 0; m < 8; m++) {
        v[m].x *= e.x; v[m].y *= e.y; v[m].z *= e.z; v[m].w *= e.w;
        stg_cs(out4 + i0 + m * SSTRIDE, v[m]);
    }
}

// ---------------------------------------------------------------------------
extern "C" void kernel_launch(void* const* d_in, const int* in_sizes, int n_in,
                              void* d_out, int out_size)
{
    const float* in = (const float*)d_in[0];
    const float* W1 = (const float*)d_in[1];
    const float* b1 = (const float*)d_in[2];
    const float* W2 = (const float*)d_in[3];
    const float* b2 = (const float*)d_in[4];
    float* out = (float*)d_out;

    for (int g = 0; g < NGRP; g++) {
        se_pool_group  <<<dim3(KSPLIT, G), 256>>>(in, g);        // 784 blocks
        se_excite_group<<<G, 256>>>(W1, b1, W2, b2, g);
        se_scale_group <<<dim3(SBLK, G), 256>>>(in, out, g);     // 784 blocks
    }
}

// round 10
// speedup vs baseline: 1.3019x; 1.3019x over previous
#include <cuda_runtime.h>
#include <math.h>

// SE block: B=32, H=W=56 (HW=3136), C=256, R=16, fp32 NHWC.
// out = in * sigmoid(relu(mean_hw(in) @ W1 + b1) @ W2 + b2)
//
// R9 (= R8 resubmit; prior run died to a container infra failure):
// 2 groups x 16 batches (51.4 MB/group, L2-resident). 5 launches:
//   pool(g0) -> excite(g0) -> [scale(g0) || pool(g1)] -> excite(g1) -> scale(g1)
// The middle kernel interleaves scale/pool roles on blockIdx.x parity so the
// g0 write stream and g1 read stream share the chip concurrently. st.cs on
// output keeps the pooled group resident for its scale pass.

#define Bb      32
#define G       16          // batches per group
#define HW      3136
#define Cc      256
#define CR      16
#define CQ      64          // C/4 float4 quads per position
#define KS      98          // pool chunks per batch
#define CHUNK   32          // 3136 / 98, exact
#define SSTR    (98 * 256)  // scale stride in quads; % 64 == 0

__device__ float g_partial[Bb * KS * Cc];   // 3.2 MB scratch
__device__ float g_exc[Bb * Cc];            // 32 KB excitation

__device__ __forceinline__ void stg_cs(float4* p, float4 v) {
    asm volatile("st.global.cs.v4.f32 [%0], {%1,%2,%3,%4};"
                 :: "l"(p), "f"(v.x), "f"(v.y), "f"(v.z), "f"(v.w) : "memory");
}

// ---- pool body: batch b, chunk k (32 positions), 256 threads --------------
__device__ __forceinline__ void pool_body(const float* __restrict__ in, int b, int k)
{
    const int tid = threadIdx.x;
    const int q   = tid & 63;
    const int pg  = tid >> 6;

    const float4* __restrict__ in4 = reinterpret_cast<const float4*>(in)
                                     + (size_t)b * HW * CQ
                                     + (size_t)(k * CHUNK + pg) * CQ + q;

    float4 a0 = make_float4(0.f, 0.f, 0.f, 0.f);
    float4 a1 = a0;
    #pragma unroll
    for (int t = 0; t < CHUNK / 4; t += 2) {          // 8 loads, 2 in flight
        float4 v0 = __ldg(in4 + (size_t)(4 * t)     * CQ);
        float4 v1 = __ldg(in4 + (size_t)(4 * t + 4) * CQ);
        a0.x += v0.x; a0.y += v0.y; a0.z += v0.z; a0.w += v0.w;
        a1.x += v1.x; a1.y += v1.y; a1.z += v1.z; a1.w += v1.w;
    }
    a0.x += a1.x; a0.y += a1.y; a0.z += a1.z; a0.w += a1.w;

    __shared__ float4 s[256];
    s[tid] = a0;
    __syncthreads();

    if (tid < 64) {
        float4 a = s[tid];
        float4 c = s[tid + 64];
        float4 d = s[tid + 128];
        float4 e = s[tid + 192];
        float4 r = make_float4(a.x + c.x + d.x + e.x,
                               a.y + c.y + d.y + e.y,
                               a.z + c.z + d.z + e.z,
                               a.w + c.w + d.w + e.w);
        reinterpret_cast<float4*>(g_partial)[(b * KS + k) * CQ + tid] = r;
    }
}

// ---- scale body: batch b, chunk sx (8 strided quads/thread) ---------------
__device__ __forceinline__ void scale_body(const float* __restrict__ in,
                                           float* __restrict__ out, int b, int sx)
{
    const int i0 = sx * 256 + threadIdx.x;

    const float4* __restrict__ in4  = reinterpret_cast<const float4*>(in)
                                      + (size_t)b * HW * CQ;
    float4* __restrict__       out4 = reinterpret_cast<float4*>(out)
                                      + (size_t)b * HW * CQ;

    const float4 e = __ldg(reinterpret_cast<const float4*>(g_exc)
                           + b * CQ + (threadIdx.x & 63));

    float4 v[8];
    #pragma unroll
    for (int m = 0; m < 8; m++)
        v[m] = __ldg(in4 + i0 + m * SSTR);

    #pragma unroll
    for (int m = 0; m < 8; m++) {
        v[m].x *= e.x; v[m].y *= e.y; v[m].z *= e.z; v[m].w *= e.w;
        stg_cs(out4 + i0 + m * SSTR, v[m]);
    }
}

// ---------------------------------------------------------------------------
__global__ void __launch_bounds__(256) se_pool(const float* __restrict__ in, int bbase)
{
    pool_body(in, bbase + blockIdx.y, blockIdx.x);
}

__global__ void __launch_bounds__(256) se_scale(const float* __restrict__ in,
                                                float* __restrict__ out, int bbase)
{
    scale_body(in, out, bbase + blockIdx.y, blockIdx.x);
}

// Fused: even x -> scale(g0) chunk x/2, odd x -> pool(g1) chunk x/2.
__global__ void __launch_bounds__(256) se_scale_pool(const float* __restrict__ in,
                                                     float* __restrict__ out,
                                                     int sbase, int pbase)
{
    const int chunk = blockIdx.x >> 1;
    if ((blockIdx.x & 1) == 0)
        scale_body(in, out, sbase + blockIdx.y, chunk);
    else
        pool_body(in, pbase + blockIdx.y, chunk);
}

// ---------------------------------------------------------------------------
// Excite: one block per batch. Reduce KS=98 partials -> mean, then
// 256 -> 16 relu -> 256 sigmoid.
// ---------------------------------------------------------------------------
__global__ void __launch_bounds__(256) se_excite(const float* __restrict__ W1,
                                                 const float* __restrict__ b1,
                                                 const float* __restrict__ W2,
                                                 const float* __restrict__ b2,
                                                 int bbase)
{
    const int b = bbase + blockIdx.x;
    const int c = threadIdx.x;

    __shared__ float sq[Cc];
    __shared__ float hs[CR];

    const float* __restrict__ part = g_partial + (size_t)b * KS * Cc + c;
    float sum = 0.f;
    #pragma unroll 7
    for (int k = 0; k < KS; k++)
        sum += part[k * Cc];
    sq[c] = sum * (1.0f / (float)HW);
    __syncthreads();

    if (c < CR) {
        float h = b1[c];
        #pragma unroll 8
        for (int i = 0; i < Cc; i++)
            h = fmaf(sq[i], W1[i * CR + c], h);
        hs[c] = fmaxf(h, 0.f);
    }
    __syncthreads();

    float e = b2[c];
    #pragma unroll
    for (int j = 0; j < CR; j++)
        e = fmaf(hs[j], W2[j * Cc + c], e);
    g_exc[b * Cc + c] = 1.0f / (1.0f + __expf(-e));
}

// ---------------------------------------------------------------------------
extern "C" void kernel_launch(void* const* d_in, const int* in_sizes, int n_in,
                              void* d_out, int out_size)
{
    const float* in = (const float*)d_in[0];
    const float* W1 = (const float*)d_in[1];
    const float* b1 = (const float*)d_in[2];
    const float* W2 = (const float*)d_in[3];
    const float* b2 = (const float*)d_in[4];
    float* out = (float*)d_out;

    se_pool      <<<dim3(KS, G), 256>>>(in, 0);              // 1568 blocks
    se_excite    <<<G, 256>>>(W1, b1, W2, b2, 0);
    se_scale_pool<<<dim3(2 * KS, G), 256>>>(in, out, 0, G);  // 3136 blocks
    se_excite    <<<G, 256>>>(W1, b1, W2, b2, G);
    se_scale     <<<dim3(KS, G), 256>>>(in, out, G);         // 1568 blocks
}

// round 11
// speedup vs baseline: 1.6509x; 1.2681x over previous
#include <cuda_runtime.h>
#include <math.h>

// SE block: B=32, H=W=56 (HW=3136), C=256, R=16, fp32 NHWC.
// out = in * sigmoid(relu(mean_hw(in) @ W1 + b1) @ W2 + b2)
//
// R10: R9 pipeline (2 groups x 16 batches, L2-resident; 5 launches:
//   pool(g0) -> excite(g0) -> [scale(g0) || pool(g1)] -> excite(g1) -> scale(g1))
// with excite rebuilt: W1 staged to smem, matvec spread over all 256 threads
// (was: 16 threads x 256 serial gmem loads -> 24 us; now ~3 us).

#define Bb      32
#define G       16          // batches per group
#define HW      3136
#define Cc      256
#define CR      16
#define CQ      64          // C/4 float4 quads per position
#define KS      98          // pool chunks per batch
#define CHUNK   32          // 3136 / 98, exact
#define SSTR    (98 * 256)  // scale stride in quads; % 64 == 0

__device__ float g_partial[Bb * KS * Cc];   // 3.2 MB scratch
__device__ float g_exc[Bb * Cc];            // 32 KB excitation

__device__ __forceinline__ void stg_cs(float4* p, float4 v) {
    asm volatile("st.global.cs.v4.f32 [%0], {%1,%2,%3,%4};"
                 :: "l"(p), "f"(v.x), "f"(v.y), "f"(v.z), "f"(v.w) : "memory");
}

// ---- pool body: batch b, chunk k (32 positions), 256 threads --------------
__device__ __forceinline__ void pool_body(const float* __restrict__ in, int b, int k)
{
    const int tid = threadIdx.x;
    const int q   = tid & 63;
    const int pg  = tid >> 6;

    const float4* __restrict__ in4 = reinterpret_cast<const float4*>(in)
                                     + (size_t)b * HW * CQ
                                     + (size_t)(k * CHUNK + pg) * CQ + q;

    float4 a0 = make_float4(0.f, 0.f, 0.f, 0.f);
    float4 a1 = a0;
    #pragma unroll
    for (int t = 0; t < CHUNK / 4; t += 2) {          // 8 loads, 2 in flight
        float4 v0 = __ldg(in4 + (size_t)(4 * t)     * CQ);
        float4 v1 = __ldg(in4 + (size_t)(4 * t + 4) * CQ);
        a0.x += v0.x; a0.y += v0.y; a0.z += v0.z; a0.w += v0.w;
        a1.x += v1.x; a1.y += v1.y; a1.z += v1.z; a1.w += v1.w;
    }
    a0.x += a1.x; a0.y += a1.y; a0.z += a1.z; a0.w += a1.w;

    __shared__ float4 s[256];
    s[tid] = a0;
    __syncthreads();

    if (tid < 64) {
        float4 a = s[tid];
        float4 c = s[tid + 64];
        float4 d = s[tid + 128];
        float4 e = s[tid + 192];
        float4 r = make_float4(a.x + c.x + d.x + e.x,
                               a.y + c.y + d.y + e.y,
                               a.z + c.z + d.z + e.z,
                               a.w + c.w + d.w + e.w);
        reinterpret_cast<float4*>(g_partial)[(b * KS + k) * CQ + tid] = r;
    }
}

// ---- scale body: batch b, chunk sx (8 strided quads/thread) ---------------
__device__ __forceinline__ void scale_body(const float* __restrict__ in,
                                           float* __restrict__ out, int b, int sx)
{
    const int i0 = sx * 256 + threadIdx.x;

    const float4* __restrict__ in4  = reinterpret_cast<const float4*>(in)
                                      + (size_t)b * HW * CQ;
    float4* __restrict__       out4 = reinterpret_cast<float4*>(out)
                                      + (size_t)b * HW * CQ;

    const float4 e = __ldg(reinterpret_cast<const float4*>(g_exc)
                           + b * CQ + (threadIdx.x & 63));

    float4 v[8];
    #pragma unroll
    for (int m = 0; m < 8; m++)
        v[m] = __ldg(in4 + i0 + m * SSTR);

    #pragma unroll
    for (int m = 0; m < 8; m++) {
        v[m].x *= e.x; v[m].y *= e.y; v[m].z *= e.z; v[m].w *= e.w;
        stg_cs(out4 + i0 + m * SSTR, v[m]);
    }
}

// ---------------------------------------------------------------------------
__global__ void __launch_bounds__(256) se_pool(const float* __restrict__ in, int bbase)
{
    pool_body(in, bbase + blockIdx.y, blockIdx.x);
}

__global__ void __launch_bounds__(256) se_scale(const float* __restrict__ in,
                                                float* __restrict__ out, int bbase)
{
    scale_body(in, out, bbase + blockIdx.y, blockIdx.x);
}

// Fused: even x -> scale(g0) chunk x/2, odd x -> pool(g1) chunk x/2.
__global__ void __launch_bounds__(256) se_scale_pool(const float* __restrict__ in,
                                                     float* __restrict__ out,
                                                     int sbase, int pbase)
{
    const int chunk = blockIdx.x >> 1;
    if ((blockIdx.x & 1) == 0)
        scale_body(in, out, sbase + blockIdx.y, chunk);
    else
        pool_body(in, pbase + blockIdx.y, chunk);
}

// ---------------------------------------------------------------------------
// Excite: one block per batch, fully parallel.
//   A: 256 threads reduce KS=98 partials (coalesced, L2-hot).
//   B: W1 (16 KB) staged to smem via float4; thread (g=tid>>4, j=tid&15)
//      accumulates a 16-element partial of h[j]; smem combine by 16 threads.
//   C: 256 threads each compute one sigmoid output (16 coalesced W2 loads).
// ---------------------------------------------------------------------------
__global__ void __launch_bounds__(256) se_excite(const float* __restrict__ W1,
                                                 const float* __restrict__ b1,
                                                 const float* __restrict__ W2,
                                                 const float* __restrict__ b2,
                                                 int bbase)
{
    const int b   = bbase + blockIdx.x;
    const int tid = threadIdx.x;

    __shared__ float sq[Cc];
    __shared__ float w1s[Cc * CR];      // 16 KB
    __shared__ float pj[CR][CR + 1];
    __shared__ float hs[CR];

    // stage W1 -> smem (1024 float4, 4 per thread, coalesced)
    {
        const float4* __restrict__ w14 = reinterpret_cast<const float4*>(W1);
        float4* w1s4 = reinterpret_cast<float4*>(w1s);
        #pragma unroll
        for (int m = 0; m < 4; m++)
            w1s4[m * 256 + tid] = __ldg(w14 + m * 256 + tid);
    }

    // A: reduce partials -> mean
    {
        const float* __restrict__ part = g_partial + (size_t)b * KS * Cc + tid;
        float sum = 0.f;
        #pragma unroll 7
        for (int k = 0; k < KS; k++)
            sum += part[k * Cc];
        sq[tid] = sum * (1.0f / (float)HW);
    }
    __syncthreads();

    // B: h = relu(sq @ W1 + b1), parallel over 256 threads
    {
        const int j = tid & 15;
        const int g = tid >> 4;
        float h = 0.f;
        #pragma unroll
        for (int i2 = 0; i2 < 16; i2++)
            h = fmaf(sq[g * 16 + i2], w1s[(g * 16 + i2) * CR + j], h);
        pj[g][j] = h;
    }
    __syncthreads();
    if (tid < CR) {
        float h = b1[tid];
        #pragma unroll
        for (int g2 = 0; g2 < 16; g2++)
            h += pj[g2][tid];
        hs[tid] = fmaxf(h, 0.f);
    }
    __syncthreads();

    // C: e = sigmoid(h @ W2 + b2)
    float e = b2[tid];
    #pragma unroll
    for (int j = 0; j < CR; j++)
        e = fmaf(hs[j], W2[j * Cc + tid], e);
    g_exc[b * Cc + tid] = 1.0f / (1.0f + __expf(-e));
}

// ---------------------------------------------------------------------------
extern "C" void kernel_launch(void* const* d_in, const int* in_sizes, int n_in,
                              void* d_out, int out_size)
{
    const float* in = (const float*)d_in[0];
    const float* W1 = (const float*)d_in[1];
    const float* b1 = (const float*)d_in[2];
    const float* W2 = (const float*)d_in[3];
    const float* b2 = (const float*)d_in[4];
    float* out = (float*)d_out;

    se_pool      <<<dim3(KS, G), 256>>>(in, 0);              // 1568 blocks
    se_excite    <<<G, 256>>>(W1, b1, W2, b2, 0);
    se_scale_pool<<<dim3(2 * KS, G), 256>>>(in, out, 0, G);  // 3136 blocks
    se_excite    <<<G, 256>>>(W1, b1, W2, b2, G);
    se_scale     <<<dim3(KS, G), 256>>>(in, out, G);         // 1568 blocks
}

// round 12
// speedup vs baseline: 2.3212x; 1.4061x over previous
#include <cuda_runtime.h>
#include <math.h>

// SE block: B=32, H=W=56 (HW=3136), C=256, R=16, fp32 NHWC.
// out = in * sigmoid(relu(mean_hw(in) @ W1 + b1) @ W2 + b2)
//
// R11: TWO launches.
//  1) se_pool_excite: R6 pool (1184 blocks = 8/SM exactly) + last-block-per-
//     batch election runs the tiny MLP in-place (partials L2-hot). Counter
//     reset by finisher -> deterministic + graph-replay safe.
//  2) se_scale: R6 scale (8 quads/thread exact cover, st.cs, reversed order).

#define Bb      32
#define HW      3136
#define Cc      256
#define CR      16
#define KSPLIT  37          // 32*37 = 1184 blocks = 8 per SM on 148 SMs
#define CHUNKP  85          // ceil(3136/37); last chunk is 76
#define CQ      64          // C/4 float4 quads per position
#define SBLK    98
#define SSTR    (SBLK * 256)  // 25088 quads; % 64 == 0

__device__ float g_partial[Bb * KSPLIT * Cc];   // ~1.2 MB scratch
__device__ float g_exc[Bb * Cc];                // 32 KB excitation
__device__ int   g_count[Bb];                   // zero at load; reset by finisher

__device__ __forceinline__ void stg_cs(float4* p, float4 v) {
    asm volatile("st.global.cs.v4.f32 [%0], {%1,%2,%3,%4};"
                 :: "l"(p), "f"(v.x), "f"(v.y), "f"(v.z), "f"(v.w) : "memory");
}

// ---------------------------------------------------------------------------
// Launch 1: pool partials + last-block excite. grid (KSPLIT, Bb) x 256.
// ---------------------------------------------------------------------------
__global__ void __launch_bounds__(256) se_pool_excite(const float* __restrict__ in,
                                                      const float* __restrict__ W1,
                                                      const float* __restrict__ b1,
                                                      const float* __restrict__ W2,
                                                      const float* __restrict__ b2)
{
    const int k   = blockIdx.x;
    const int b   = blockIdx.y;
    const int tid = threadIdx.x;
    const int q   = tid & 63;
    const int pg  = tid >> 6;

    // ---- pool: R6's proven 32-reg body -------------------------------------
    const float4* __restrict__ in4 = reinterpret_cast<const float4*>(in)
                                     + (size_t)b * HW * CQ;

    float4 a0 = make_float4(0.f, 0.f, 0.f, 0.f);
    float4 a1 = make_float4(0.f, 0.f, 0.f, 0.f);
    const int pBeg = k * CHUNKP;
    const int pEnd = (pBeg + CHUNKP < HW) ? (pBeg + CHUNKP) : HW;
    int p = pBeg + pg;
    for (; p + 4 < pEnd; p += 8) {
        float4 v0 = __ldg(&in4[(size_t)p * CQ + q]);
        float4 v1 = __ldg(&in4[(size_t)(p + 4) * CQ + q]);
        a0.x += v0.x; a0.y += v0.y; a0.z += v0.z; a0.w += v0.w;
        a1.x += v1.x; a1.y += v1.y; a1.z += v1.z; a1.w += v1.w;
    }
    if (p < pEnd) {
        float4 v0 = __ldg(&in4[(size_t)p * CQ + q]);
        a0.x += v0.x; a0.y += v0.y; a0.z += v0.z; a0.w += v0.w;
    }
    a0.x += a1.x; a0.y += a1.y; a0.z += a1.z; a0.w += a1.w;

    __shared__ float4 s4[256];
    s4[tid] = a0;
    __syncthreads();

    if (tid < 64) {
        float4 a = s4[tid];
        float4 c = s4[tid + 64];
        float4 d = s4[tid + 128];
        float4 e = s4[tid + 192];
        float4 r = make_float4(a.x + c.x + d.x + e.x,
                               a.y + c.y + d.y + e.y,
                               a.z + c.z + d.z + e.z,
                               a.w + c.w + d.w + e.w);
        reinterpret_cast<float4*>(g_partial)[(b * KSPLIT + k) * CQ + tid] = r;
    }
    __syncthreads();

    // ---- last-block election for this batch --------------------------------
    __shared__ int sLast;
    if (tid == 0) {
        __threadfence();                               // partials visible
        int ticket = atomicAdd(&g_count[b], 1);
        sLast = (ticket == KSPLIT - 1);
        if (sLast) g_count[b] = 0;                     // reset for next replay
    }
    __syncthreads();
    if (!sLast) return;
    __threadfence();                                   // order reads after elect

    // ---- excite for batch b (256 threads, partials L2-hot) -----------------
    __shared__ float sq[Cc];
    __shared__ float pj[16][CR + 1];
    __shared__ float hs[CR];

    {
        const float* __restrict__ part = g_partial + (size_t)b * KSPLIT * Cc + tid;
        float sum = 0.f;
        #pragma unroll
        for (int kk = 0; kk < KSPLIT; kk++)
            sum += part[kk * Cc];
        sq[tid] = sum * (1.0f / (float)HW);
    }
    __syncthreads();

    {   // h-partials: thread (g = tid>>4, j = tid&15) covers 16 input channels
        const int j = tid & 15;
        const int g = tid >> 4;
        float h = 0.f;
        #pragma unroll
        for (int i2 = 0; i2 < 16; i2++)
            h = fmaf(sq[g * 16 + i2], __ldg(&W1[(g * 16 + i2) * CR + j]), h);
        pj[g][j] = h;
    }
    __syncthreads();
    if (tid < CR) {
        float h = __ldg(&b1[tid]);
        #pragma unroll
        for (int g2 = 0; g2 < 16; g2++)
            h += pj[g2][tid];
        hs[tid] = fmaxf(h, 0.f);
    }
    __syncthreads();

    float e = __ldg(&b2[tid]);
    #pragma unroll
    for (int j = 0; j < CR; j++)
        e = fmaf(hs[j], __ldg(&W2[j * Cc + tid]), e);
    g_exc[b * Cc + tid] = 1.0f / (1.0f + __expf(-e));
}

// ---------------------------------------------------------------------------
// Launch 2: out = in * exc[b,c]. grid (SBLK, Bb) x 256, 8 quads/thread at
// stride 25088 (%64==0 -> one excitation quad per thread). st.cs output,
// reversed traversal (most-recently-pooled lines first).
// ---------------------------------------------------------------------------
__global__ void __launch_bounds__(256) se_scale(const float* __restrict__ in,
                                                float* __restrict__ out)
{
    const int b  = (Bb - 1)   - blockIdx.y;
    const int bx = (SBLK - 1) - blockIdx.x;
    const int i0 = bx * 256 + threadIdx.x;

    const float4* __restrict__ in4  = reinterpret_cast<const float4*>(in)
                                      + (size_t)b * HW * CQ;
    float4* __restrict__       out4 = reinterpret_cast<float4*>(out)
                                      + (size_t)b * HW * CQ;

    const float4 e = *(reinterpret_cast<const float4*>(g_exc)
                       + b * CQ + (threadIdx.x & 63));

    float4 v[8];
    #pragma unroll
    for (int m = 0; m < 8; m++)
        v[m] = __ldg(in4 + i0 + m * SSTR);

    #pragma unroll
    for (int m = 0; m < 8; m++) {
        v[m].x *= e.x; v[m].y *= e.y; v[m].z *= e.z; v[m].w *= e.w;
        stg_cs(out4 + i0 + m * SSTR, v[m]);
    }
}

// ---------------------------------------------------------------------------
extern "C" void kernel_launch(void* const* d_in, const int* in_sizes, int n_in,
                              void* d_out, int out_size)
{
    const float* in = (const float*)d_in[0];
    const float* W1 = (const float*)d_in[1];
    const float* b1 = (const float*)d_in[2];
    const float* W2 = (const float*)d_in[3];
    const float* b2 = (const float*)d_in[4];
    float* out = (float*)d_out;

    se_pool_excite<<<dim3(KSPLIT, Bb), 256>>>(in, W1, b1, W2, b2);  // 1184 blocks
    se_scale      <<<dim3(SBLK,   Bb), 256>>>(in, out);             // 3136 blocks
}